// round 2
// baseline (speedup 1.0000x reference)
#include <cuda_runtime.h>

// Problem constants
#define LSEQ   2048
#define NB     2
#define DMODEL 2048
#define NQKV   3072
#define KVW    512
#define HD     64

// Scratch (device globals; no allocation allowed)
__device__ float g_Q [NB * LSEQ * DMODEL];  // per batch: (L, 2048) row-major == q-flat
__device__ float g_K [NB * LSEQ * KVW];     // per batch: (L, 512)  row-major == k-flat
__device__ float g_V [NB * LSEQ * KVW];
__device__ float g_AO[NB * LSEQ * DMODEL];  // attention output, (L, 2048), head gh at cols gh*64..

// ===================== SGEMM (fp32, 128x128x16, 8x8 microtile) =====================
#define BM 128
#define BN 128
#define BK 16
#define TM 8
#define TN 8
#define GEMM_THREADS 256

// MODE 1: A = x (param), epilogue splits columns into g_Q/g_K/g_V
// MODE 0: A = g_AO, epilogue writes C (param)
template<int MODE>
__global__ __launch_bounds__(GEMM_THREADS)
void sgemm_kernel(const float* __restrict__ A_, const float* __restrict__ Bm,
                  float* __restrict__ C_, int M, int N, int K)
{
    __shared__ float As[BK][BM + 4];   // transposed A tile: As[k][m]
    __shared__ float Bs[BK][BN + 4];   // natural B tile:    Bs[k][n]

    const int tid = threadIdx.x;
    const int brow = blockIdx.y * BM;
    const int bcol = blockIdx.x * BN;
    const int bz   = blockIdx.z;

    const float* A = (MODE == 1 ? A_ : g_AO) + (size_t)bz * M * K;

    const int rowA = tid >> 2;          // 0..63
    const int colA = (tid & 3) << 2;    // 0,4,8,12
    const int rowB = tid >> 5;          // 0..7
    const int colB = (tid & 31) << 2;   // 0..124

    const int tRow = (tid >> 4) * TM;   // 0..120
    const int tCol = (tid & 15) * TN;   // 0..120

    float acc[TM][TN];
    #pragma unroll
    for (int i = 0; i < TM; i++)
        #pragma unroll
        for (int j = 0; j < TN; j++) acc[i][j] = 0.f;

    for (int k0 = 0; k0 < K; k0 += BK) {
        #pragma unroll
        for (int p = 0; p < 2; p++) {
            int r = rowA + 64 * p;
            float4 v = *(const float4*)(A + (size_t)(brow + r) * K + k0 + colA);
            As[colA + 0][r] = v.x;
            As[colA + 1][r] = v.y;
            As[colA + 2][r] = v.z;
            As[colA + 3][r] = v.w;
        }
        #pragma unroll
        for (int p = 0; p < 2; p++) {
            int r = rowB + 8 * p;
            *(float4*)&Bs[r][colB] = *(const float4*)(Bm + (size_t)(k0 + r) * N + bcol + colB);
        }
        __syncthreads();

        #pragma unroll
        for (int k = 0; k < BK; k++) {
            float rM[TM], rN[TN];
            *(float4*)(rM)     = *(const float4*)&As[k][tRow];
            *(float4*)(rM + 4) = *(const float4*)&As[k][tRow + 4];
            *(float4*)(rN)     = *(const float4*)&Bs[k][tCol];
            *(float4*)(rN + 4) = *(const float4*)&Bs[k][tCol + 4];
            #pragma unroll
            for (int i = 0; i < TM; i++)
                #pragma unroll
                for (int j = 0; j < TN; j++)
                    acc[i][j] += rM[i] * rN[j];
        }
        __syncthreads();
    }

    if (MODE == 0) {
        float* C = C_ + (size_t)bz * M * N;
        #pragma unroll
        for (int i = 0; i < TM; i++) {
            int r = brow + tRow + i;
            #pragma unroll
            for (int jv = 0; jv < TN; jv += 4) {
                float4 v = make_float4(acc[i][jv], acc[i][jv+1], acc[i][jv+2], acc[i][jv+3]);
                *(float4*)(C + (size_t)r * N + bcol + tCol + jv) = v;
            }
        }
    } else {
        // Split-columns epilogue: [0,2048) -> Q, [2048,2560) -> K, [2560,3072) -> V.
        // BN=128 and the boundaries are multiples of 128, so target is block-uniform.
        const int col = bcol + tCol;
        float* dst; int ldd, c0;
        if (col < DMODEL)            { dst = g_Q + (size_t)bz * LSEQ * DMODEL; ldd = DMODEL; c0 = col; }
        else if (col < DMODEL + KVW) { dst = g_K + (size_t)bz * LSEQ * KVW;   ldd = KVW;   c0 = col - DMODEL; }
        else                         { dst = g_V + (size_t)bz * LSEQ * KVW;   ldd = KVW;   c0 = col - DMODEL - KVW; }
        #pragma unroll
        for (int i = 0; i < TM; i++) {
            int r = brow + tRow + i;
            #pragma unroll
            for (int jv = 0; jv < TN; jv += 4) {
                float4 v = make_float4(acc[i][jv], acc[i][jv+1], acc[i][jv+2], acc[i][jv+3]);
                *(float4*)(dst + (size_t)r * ldd + c0 + jv) = v;
            }
        }
    }
}

// ===================== Flash attention (fp32, Br=Bc=64, d=64) =====================
// Grid: (qtile=32, gh=32, b=2). 256 threads; thread (ty,tx) owns a 4x4 S/O microtile.
#define AT_THREADS 256
// dynamic smem layout (floats): Qs[64][64] | Ks[64][68] | Vs[64][64] | Ps[64][68]
#define QS_OFF 0
#define KS_OFF (64 * 64)
#define VS_OFF (KS_OFF + 64 * 68)
#define PS_OFF (VS_OFF + 64 * 64)
#define ATTN_SMEM_FLOATS (PS_OFF + 64 * 68)
#define ATTN_SMEM_BYTES (ATTN_SMEM_FLOATS * 4)

__global__ __launch_bounds__(AT_THREADS)
void flash_attn_kernel()
{
    extern __shared__ float sm[];
    float* Qs = sm + QS_OFF;   // [d][r], stride 64
    float* Ks = sm + KS_OFF;   // [d][j], stride 68 (padded: per-tile transposed stores)
    float* Vs = sm + VS_OFF;   // [j][d], stride 64
    float* Ps = sm + PS_OFF;   // [j][r], stride 68

    const int qt = blockIdx.x;
    const int gh = blockIdx.y;
    const int b  = blockIdx.z;
    const int h  = gh & 7;     // kv head = gh % 8 (from the reshape structure)

    const float* Qg = g_Q + (size_t)b * LSEQ * DMODEL + (size_t)gh * LSEQ * HD;
    const float* Kg = g_K + (size_t)b * LSEQ * KVW    + (size_t)h  * LSEQ * HD;
    const float* Vg = g_V + (size_t)b * LSEQ * KVW    + (size_t)h  * LSEQ * HD;
    float* AO = g_AO + (size_t)b * LSEQ * DMODEL;

    const int tid = threadIdx.x;
    const int tx = tid & 15;   // 16 col-groups of 4
    const int ty = tid >> 4;   // 16 row-groups of 4
    const int q0 = qt * 64;

    const int lr = tid >> 2;        // 0..63 (load row)
    const int lc = (tid & 3) << 2;  // 0,4,8,12 (load d-col base)

    // Load Q tile transposed into Qs[d][r]
    #pragma unroll
    for (int p = 0; p < 4; p++) {
        int d = lc + 16 * p;
        float4 v = *(const float4*)(Qg + (size_t)(q0 + lr) * HD + d);
        Qs[(d + 0) * 64 + lr] = v.x;
        Qs[(d + 1) * 64 + lr] = v.y;
        Qs[(d + 2) * 64 + lr] = v.z;
        Qs[(d + 3) * 64 + lr] = v.w;
    }

    float m_i[4], l_i[4], o[4][4];
    #pragma unroll
    for (int i = 0; i < 4; i++) {
        m_i[i] = -1e30f; l_i[i] = 0.f;
        #pragma unroll
        for (int j = 0; j < 4; j++) o[i][j] = 0.f;
    }

    for (int jt = 0; jt <= qt; jt++) {
        __syncthreads();  // Qs visible (iter 0); prev-iter Ks/Vs/Ps reads complete

        // Load K tile transposed (Ks[d][j]) and V tile natural (Vs[j][d])
        #pragma unroll
        for (int p = 0; p < 4; p++) {
            int d = lc + 16 * p;
            float4 kv = *(const float4*)(Kg + (size_t)(jt * 64 + lr) * HD + d);
            Ks[(d + 0) * 68 + lr] = kv.x;
            Ks[(d + 1) * 68 + lr] = kv.y;
            Ks[(d + 2) * 68 + lr] = kv.z;
            Ks[(d + 3) * 68 + lr] = kv.w;
            float4 vv = *(const float4*)(Vg + (size_t)(jt * 64 + lr) * HD + d);
            *(float4*)&Vs[lr * 64 + d] = vv;
        }
        __syncthreads();

        // S = Q K^T  (4x4 per thread)
        float s[4][4];
        #pragma unroll
        for (int i = 0; i < 4; i++)
            #pragma unroll
            for (int j = 0; j < 4; j++) s[i][j] = 0.f;

        #pragma unroll 8
        for (int k = 0; k < 64; k++) {
            float a[4], bb[4];
            *(float4*)a  = *(const float4*)&Qs[k * 64 + ty * 4];
            *(float4*)bb = *(const float4*)&Ks[k * 68 + tx * 4];
            #pragma unroll
            for (int i = 0; i < 4; i++)
                #pragma unroll
                for (int j = 0; j < 4; j++)
                    s[i][j] += a[i] * bb[j];
        }

        // Online softmax (per-row over 16 lanes; warp holds 2 row-groups of 16 lanes)
        const bool diag = (jt == qt);
        #pragma unroll
        for (int i = 0; i < 4; i++) {
            const int lrow = ty * 4 + i;  // local row; causal in local coords on diagonal tile
            float mx = -1e30f;
            #pragma unroll
            for (int j = 0; j < 4; j++) {
                float v = s[i][j] * 0.125f;          // 1/sqrt(64)
                if (diag && (tx * 4 + j > lrow)) v = -1e30f;
                s[i][j] = v;
                mx = fmaxf(mx, v);
            }
            #pragma unroll
            for (int off = 8; off; off >>= 1)
                mx = fmaxf(mx, __shfl_xor_sync(0xffffffffu, mx, off));
            const float mnew  = fmaxf(m_i[i], mx);
            const float alpha = __expf(m_i[i] - mnew);
            float rs = 0.f;
            #pragma unroll
            for (int j = 0; j < 4; j++) {
                s[i][j] = __expf(s[i][j] - mnew);
                rs += s[i][j];
            }
            #pragma unroll
            for (int off = 8; off; off >>= 1)
                rs += __shfl_xor_sync(0xffffffffu, rs, off);
            l_i[i] = l_i[i] * alpha + rs;
            m_i[i] = mnew;
            #pragma unroll
            for (int j = 0; j < 4; j++) o[i][j] *= alpha;
        }

        // Store P transposed: Ps[j][r]
        #pragma unroll
        for (int j = 0; j < 4; j++)
            #pragma unroll
            for (int i = 0; i < 4; i++)
                Ps[(tx * 4 + j) * 68 + ty * 4 + i] = s[i][j];
        __syncthreads();

        // O += P V
        #pragma unroll 8
        for (int j = 0; j < 64; j++) {
            float a[4], bb[4];
            *(float4*)a  = *(const float4*)&Ps[j * 68 + ty * 4];
            *(float4*)bb = *(const float4*)&Vs[j * 64 + tx * 4];
            #pragma unroll
            for (int i = 0; i < 4; i++)
                #pragma unroll
                for (int k = 0; k < 4; k++)
                    o[i][k] += a[i] * bb[k];
        }
    }

    // Epilogue: normalize rows, write AO[row][gh*64 + d]
    #pragma unroll
    for (int i = 0; i < 4; i++) {
        const float inv = 1.f / l_i[i];
        float4 v = make_float4(o[i][0]*inv, o[i][1]*inv, o[i][2]*inv, o[i][3]*inv);
        *(float4*)(AO + (size_t)(q0 + ty * 4 + i) * DMODEL + gh * HD + tx * 4) = v;
    }
}

// ===================== Launch =====================
extern "C" void kernel_launch(void* const* d_in, const int* in_sizes, int n_in,
                              void* d_out, int out_size)
{
    const float* x    = (const float*)d_in[0];   // (2, 2048, 2048)
    // d_in[1] is the causal mask; its effect (-1e9 additive tril) is reproduced exactly
    // by skipping j > l (exp underflows to 0 in fp32), so it is not read.
    const float* Wqkv = (const float*)d_in[2];   // (2048, 3072)
    const float* Wout = (const float*)d_in[3];   // (2048, 2048)
    float* out = (float*)d_out;                  // (2, 2048, 2048) fp32

    // Opt-in for 66KB dynamic smem (idempotent; not a stream-ordered op, capture-safe).
    (void)cudaFuncSetAttribute(flash_attn_kernel,
                               cudaFuncAttributeMaxDynamicSharedMemorySize, ATTN_SMEM_BYTES);

    // 1) qkv = x @ W_qkv, split-stored into g_Q / g_K / g_V
    sgemm_kernel<1><<<dim3(NQKV / BN, LSEQ / BM, NB), GEMM_THREADS>>>(
        x, Wqkv, nullptr, LSEQ, NQKV, DMODEL);

    // 2) causal flash attention per (qtile, head, batch) into g_AO
    flash_attn_kernel<<<dim3(LSEQ / 64, 32, NB), AT_THREADS, ATTN_SMEM_BYTES>>>();

    // 3) out = g_AO @ W_out
    sgemm_kernel<0><<<dim3(DMODEL / BN, LSEQ / BM, NB), GEMM_THREADS>>>(
        nullptr, Wout, out, LSEQ, DMODEL, DMODEL);
}

// round 5
// speedup vs baseline: 1.6141x; 1.6141x over previous
#include <cuda_runtime.h>
#include <cuda_bf16.h>
#include <cstdint>

// Problem constants
#define LSEQ   2048
#define NB     2
#define DMODEL 2048
#define NQKV   3072
#define KVW    512
#define HD     64
#define MROWS  (NB * LSEQ)   // 4096

// ---------------- scratch (device globals; no allocation allowed) ----------------
__device__ float g_Q [NB * LSEQ * DMODEL];
__device__ float g_K [NB * LSEQ * KVW];
__device__ float g_V [NB * LSEQ * KVW];
__device__ float g_AO[NB * LSEQ * DMODEL];

// bf16 hi/lo splits
__device__ __nv_bfloat16 g_xh [MROWS * DMODEL], g_xl [MROWS * DMODEL];
__device__ __nv_bfloat16 g_aoh[MROWS * DMODEL], g_aol[MROWS * DMODEL];
__device__ __nv_bfloat16 g_wqh[NQKV * DMODEL],  g_wql[NQKV * DMODEL];    // W_qkv^T (N,K)
__device__ __nv_bfloat16 g_woh[DMODEL * DMODEL], g_wol[DMODEL * DMODEL]; // W_out^T (N,K)

// ---------------- PTX helpers (portable ISA: sm_80+) ----------------
__device__ __forceinline__ uint32_t s2u(const void* p) {
    uint32_t a;
    asm("{ .reg .u64 t; cvta.to.shared.u64 t, %1; cvt.u32.u64 %0, t; }" : "=r"(a) : "l"(p));
    return a;
}

__device__ __forceinline__ void ldm4(uint32_t* r, uint32_t addr) {
    asm volatile("ldmatrix.sync.aligned.m8n8.x4.shared.b16 {%0,%1,%2,%3}, [%4];"
                 : "=r"(r[0]), "=r"(r[1]), "=r"(r[2]), "=r"(r[3]) : "r"(addr));
}

__device__ __forceinline__ void mma16816(float* d, const uint32_t* a, const uint32_t* b) {
    asm volatile("mma.sync.aligned.m16n8k16.row.col.f32.bf16.bf16.f32 "
                 "{%0,%1,%2,%3}, {%4,%5,%6,%7}, {%8,%9}, {%0,%1,%2,%3};"
                 : "+f"(d[0]), "+f"(d[1]), "+f"(d[2]), "+f"(d[3])
                 : "r"(a[0]), "r"(a[1]), "r"(a[2]), "r"(a[3]), "r"(b[0]), "r"(b[1]));
}

#define CPASYNC(dst, src) \
    asm volatile("cp.async.cg.shared.global [%0], [%1], 16;" :: "r"(dst), "l"(src))
#define CPCOMMIT() asm volatile("cp.async.commit_group;")
#define CPWAIT(n)  asm volatile("cp.async.wait_group %0;" :: "n"(n))

// ---------------- conversion kernels ----------------
__global__ void split_convert(const float* __restrict__ in_x, int n4, int sel)
{
    __nv_bfloat16* hi = sel ? g_aoh : g_xh;
    __nv_bfloat16* lo = sel ? g_aol : g_xl;
    const float* src = sel ? (const float*)g_AO : in_x;
    int i = blockIdx.x * blockDim.x + threadIdx.x;
    if (i >= n4) return;
    float4 v = ((const float4*)src)[i];
    float f[4] = {v.x, v.y, v.z, v.w};
    __nv_bfloat16 h[4], l[4];
    #pragma unroll
    for (int j = 0; j < 4; j++) {
        h[j] = __float2bfloat16(f[j]);
        l[j] = __float2bfloat16(f[j] - __bfloat162float(h[j]));
    }
    *(uint2*)(hi + 4 * (size_t)i) = *(uint2*)h;
    *(uint2*)(lo + 4 * (size_t)i) = *(uint2*)l;
}

// W (K=2048 rows, N cols) fp32 -> W^T (N rows, K cols) bf16 hi/lo
__global__ void transpose_convert(const float* __restrict__ in, int N, int sel)
{
    __shared__ float t[32][33];
    __nv_bfloat16* hi = sel ? g_woh : g_wqh;
    __nv_bfloat16* lo = sel ? g_wol : g_wql;
    const int n0 = blockIdx.x * 32, k0 = blockIdx.y * 32;
    const int tx = threadIdx.x, ty = threadIdx.y;
    #pragma unroll
    for (int j = 0; j < 32; j += 8)
        t[ty + j][tx] = in[(size_t)(k0 + ty + j) * N + n0 + tx];
    __syncthreads();
    #pragma unroll
    for (int j = 0; j < 32; j += 8) {
        float v = t[tx][ty + j];
        int n = n0 + ty + j, k = k0 + tx;
        __nv_bfloat16 h = __float2bfloat16(v);
        hi[(size_t)n * DMODEL + k] = h;
        lo[(size_t)n * DMODEL + k] = __float2bfloat16(v - __bfloat162float(h));
    }
}

// ---------------- mma.sync bf16x3 GEMM: 128x128 block, K=2048 ----------------
// A: (M,K) row-major hi/lo.  B: (N,K) row-major (= col-major for .row.col) hi/lo.
// MODE 1: A=x, B=Wqkv^T, epilogue splits into g_Q/g_K/g_V.  MODE 0: A=AO, B=Wout^T -> Cout.
#define BKC 32
#define TROW 80                       // smem bytes per 32-bf16 row (padded; ldmatrix conflict-free)
#define TILE_BYTES (128 * TROW)       // 10240
#define STAGE_BYTES (4 * TILE_BYTES)  // A_hi, A_lo, B_hi, B_lo
#define GSMEM (2 * STAGE_BYTES)       // 81920
#define NCHUNK (DMODEL / BKC)         // 64

template<int MODE>
__global__ void __launch_bounds__(256)
gemm_mma(float* __restrict__ Cout)
{
    extern __shared__ char smem[];
    const uint32_t sb = s2u(smem);
    const int tid = threadIdx.x, wid = tid >> 5, lane = tid & 31;
    const int wm = wid >> 1, wn = wid & 1;

    const __nv_bfloat16 *Ah, *Al, *Bh, *Bl;
    if (MODE == 1) { Ah = g_xh;  Al = g_xl;  Bh = g_wqh; Bl = g_wql; }
    else           { Ah = g_aoh; Al = g_aol; Bh = g_woh; Bl = g_wol; }

    const int bm = blockIdx.y * 128;
    const int bn = blockIdx.x * 128;

    float acc[2][8][4];
    #pragma unroll
    for (int i = 0; i < 2; i++)
        #pragma unroll
        for (int j = 0; j < 8; j++)
            #pragma unroll
            for (int q = 0; q < 4; q++) acc[i][j][q] = 0.f;

    // per-thread load coords: 2 chunks of 16B per tile (128 rows x 4 sixteen-byte cols)
    const int lrow0 = tid >> 2;            // 0..63
    const int lck   = tid & 3;             // 0..3

    auto issue_load = [&](int stage, int c) {
        const uint32_t so = sb + (uint32_t)stage * STAGE_BYTES;
        const int kc = c * BKC;
        const __nv_bfloat16* srcs[4] = {Ah, Al, Bh, Bl};
        #pragma unroll
        for (int t = 0; t < 4; t++) {
            const int rb = (t < 2) ? bm : bn;
            const __nv_bfloat16* s = srcs[t];
            #pragma unroll
            for (int half = 0; half < 2; half++) {
                int row = lrow0 + half * 64;
                uint32_t dst = so + (uint32_t)t * TILE_BYTES + row * TROW + lck * 16;
                const void* src = s + (size_t)(rb + row) * DMODEL + kc + lck * 8;
                CPASYNC(dst, src);
            }
        }
        CPCOMMIT();
    };

    issue_load(0, 0);

    for (int c = 0; c < NCHUNK; c++) {
        if (c + 1 < NCHUNK) issue_load((c + 1) & 1, c + 1);
        if (c + 1 < NCHUNK) { CPWAIT(1); } else { CPWAIT(0); }
        __syncthreads();

        const uint32_t so = sb + (uint32_t)(c & 1) * STAGE_BYTES;
        const uint32_t aq = (lane & 7) + ((lane >> 3) & 1) * 8;  // row add for A x4
        const uint32_t ak = (lane >> 4) * 8;                     // k add for A x4
        const uint32_t bq = (lane & 7) + ((lane >> 4)) * 8;      // row add for B x4 (q>>1)
        const uint32_t bk = ((lane >> 3) & 1) * 8;               // k add for B x4 (q&1)

        #pragma unroll
        for (int ks = 0; ks < 2; ks++) {
            uint32_t afh[2][4], afl[2][4];
            #pragma unroll
            for (int i = 0; i < 2; i++) {
                uint32_t addr = so + (wm * 32 + i * 16 + aq) * TROW + (ks * 16 + ak) * 2;
                ldm4(afh[i], addr);
                ldm4(afl[i], addr + TILE_BYTES);
            }
            uint32_t bfh[8][2], bfl[8][2];
            #pragma unroll
            for (int jj = 0; jj < 4; jj++) {
                uint32_t addr = so + 2 * TILE_BYTES
                              + (wn * 64 + jj * 16 + bq) * TROW + (ks * 16 + bk) * 2;
                uint32_t r[4];
                ldm4(r, addr);
                bfh[jj*2][0] = r[0]; bfh[jj*2][1] = r[1];
                bfh[jj*2+1][0] = r[2]; bfh[jj*2+1][1] = r[3];
                ldm4(r, addr + TILE_BYTES);
                bfl[jj*2][0] = r[0]; bfl[jj*2][1] = r[1];
                bfl[jj*2+1][0] = r[2]; bfl[jj*2+1][1] = r[3];
            }
            #pragma unroll
            for (int i = 0; i < 2; i++)
                #pragma unroll
                for (int j = 0; j < 8; j++) {
                    mma16816(acc[i][j], afh[i], bfh[j]);   // hi*hi
                    mma16816(acc[i][j], afh[i], bfl[j]);   // hi*lo
                    mma16816(acc[i][j], afl[i], bfh[j]);   // lo*hi
                }
        }
        __syncthreads();
    }

    // ---- epilogue ----
    const int g = lane >> 2, tg = lane & 3;
    if (MODE == 0) {
        #pragma unroll
        for (int i = 0; i < 2; i++) {
            const int r0 = bm + wm * 32 + i * 16 + g;
            #pragma unroll
            for (int j = 0; j < 8; j++) {
                const int cc = bn + wn * 64 + j * 8 + tg * 2;
                *(float2*)(Cout + (size_t)r0 * DMODEL + cc)       = make_float2(acc[i][j][0], acc[i][j][1]);
                *(float2*)(Cout + (size_t)(r0 + 8) * DMODEL + cc) = make_float2(acc[i][j][2], acc[i][j][3]);
            }
        }
    } else {
        // split by output column region (block-uniform: boundaries are multiples of 128)
        const int b = bm >> 11;                 // batch
        const int rloc = bm & (LSEQ - 1);
        float* dstb; int ldd, c0;
        if (bn < DMODEL)            { dstb = g_Q + (size_t)b * LSEQ * DMODEL; ldd = DMODEL; c0 = bn; }
        else if (bn < DMODEL + KVW) { dstb = g_K + (size_t)b * LSEQ * KVW;   ldd = KVW;    c0 = bn - DMODEL; }
        else                        { dstb = g_V + (size_t)b * LSEQ * KVW;   ldd = KVW;    c0 = bn - DMODEL - KVW; }
        #pragma unroll
        for (int i = 0; i < 2; i++) {
            const int r0 = rloc + wm * 32 + i * 16 + g;
            #pragma unroll
            for (int j = 0; j < 8; j++) {
                const int cc = c0 + wn * 64 + j * 8 + tg * 2;
                *(float2*)(dstb + (size_t)r0 * ldd + cc)       = make_float2(acc[i][j][0], acc[i][j][1]);
                *(float2*)(dstb + (size_t)(r0 + 8) * ldd + cc) = make_float2(acc[i][j][2], acc[i][j][3]);
            }
        }
    }
}

// ===================== Flash attention (fp32, Br=Bc=64, d=64) — unchanged =====================
#define AT_THREADS 256
#define QS_OFF 0
#define KS_OFF (64 * 64)
#define VS_OFF (KS_OFF + 64 * 68)
#define PS_OFF (VS_OFF + 64 * 64)
#define ATTN_SMEM_FLOATS (PS_OFF + 64 * 68)
#define ATTN_SMEM_BYTES (ATTN_SMEM_FLOATS * 4)

__global__ __launch_bounds__(AT_THREADS)
void flash_attn_kernel()
{
    extern __shared__ float sm[];
    float* Qs = sm + QS_OFF;
    float* Ks = sm + KS_OFF;
    float* Vs = sm + VS_OFF;
    float* Ps = sm + PS_OFF;

    const int qt = blockIdx.x;
    const int gh = blockIdx.y;
    const int b  = blockIdx.z;
    const int h  = gh & 7;

    const float* Qg = g_Q + (size_t)b * LSEQ * DMODEL + (size_t)gh * LSEQ * HD;
    const float* Kg = g_K + (size_t)b * LSEQ * KVW    + (size_t)h  * LSEQ * HD;
    const float* Vg = g_V + (size_t)b * LSEQ * KVW    + (size_t)h  * LSEQ * HD;
    float* AO = g_AO + (size_t)b * LSEQ * DMODEL;

    const int tid = threadIdx.x;
    const int tx = tid & 15;
    const int ty = tid >> 4;
    const int q0 = qt * 64;

    const int lr = tid >> 2;
    const int lc = (tid & 3) << 2;

    #pragma unroll
    for (int p = 0; p < 4; p++) {
        int d = lc + 16 * p;
        float4 v = *(const float4*)(Qg + (size_t)(q0 + lr) * HD + d);
        Qs[(d + 0) * 64 + lr] = v.x;
        Qs[(d + 1) * 64 + lr] = v.y;
        Qs[(d + 2) * 64 + lr] = v.z;
        Qs[(d + 3) * 64 + lr] = v.w;
    }

    float m_i[4], l_i[4], o[4][4];
    #pragma unroll
    for (int i = 0; i < 4; i++) {
        m_i[i] = -1e30f; l_i[i] = 0.f;
        #pragma unroll
        for (int j = 0; j < 4; j++) o[i][j] = 0.f;
    }

    for (int jt = 0; jt <= qt; jt++) {
        __syncthreads();

        #pragma unroll
        for (int p = 0; p < 4; p++) {
            int d = lc + 16 * p;
            float4 kv = *(const float4*)(Kg + (size_t)(jt * 64 + lr) * HD + d);
            Ks[(d + 0) * 68 + lr] = kv.x;
            Ks[(d + 1) * 68 + lr] = kv.y;
            Ks[(d + 2) * 68 + lr] = kv.z;
            Ks[(d + 3) * 68 + lr] = kv.w;
            float4 vv = *(const float4*)(Vg + (size_t)(jt * 64 + lr) * HD + d);
            *(float4*)&Vs[lr * 64 + d] = vv;
        }
        __syncthreads();

        float s[4][4];
        #pragma unroll
        for (int i = 0; i < 4; i++)
            #pragma unroll
            for (int j = 0; j < 4; j++) s[i][j] = 0.f;

        #pragma unroll 8
        for (int k = 0; k < 64; k++) {
            float a[4], bb[4];
            *(float4*)a  = *(const float4*)&Qs[k * 64 + ty * 4];
            *(float4*)bb = *(const float4*)&Ks[k * 68 + tx * 4];
            #pragma unroll
            for (int i = 0; i < 4; i++)
                #pragma unroll
                for (int j = 0; j < 4; j++)
                    s[i][j] += a[i] * bb[j];
        }

        const bool diag = (jt == qt);
        #pragma unroll
        for (int i = 0; i < 4; i++) {
            const int lrow = ty * 4 + i;
            float mx = -1e30f;
            #pragma unroll
            for (int j = 0; j < 4; j++) {
                float v = s[i][j] * 0.125f;
                if (diag && (tx * 4 + j > lrow)) v = -1e30f;
                s[i][j] = v;
                mx = fmaxf(mx, v);
            }
            #pragma unroll
            for (int off = 8; off; off >>= 1)
                mx = fmaxf(mx, __shfl_xor_sync(0xffffffffu, mx, off));
            const float mnew  = fmaxf(m_i[i], mx);
            const float alpha = __expf(m_i[i] - mnew);
            float rs = 0.f;
            #pragma unroll
            for (int j = 0; j < 4; j++) {
                s[i][j] = __expf(s[i][j] - mnew);
                rs += s[i][j];
            }
            #pragma unroll
            for (int off = 8; off; off >>= 1)
                rs += __shfl_xor_sync(0xffffffffu, rs, off);
            l_i[i] = l_i[i] * alpha + rs;
            m_i[i] = mnew;
            #pragma unroll
            for (int j = 0; j < 4; j++) o[i][j] *= alpha;
        }

        #pragma unroll
        for (int j = 0; j < 4; j++)
            #pragma unroll
            for (int i = 0; i < 4; i++)
                Ps[(tx * 4 + j) * 68 + ty * 4 + i] = s[i][j];
        __syncthreads();

        #pragma unroll 8
        for (int j = 0; j < 64; j++) {
            float a[4], bb[4];
            *(float4*)a  = *(const float4*)&Ps[j * 68 + ty * 4];
            *(float4*)bb = *(const float4*)&Vs[j * 64 + tx * 4];
            #pragma unroll
            for (int i = 0; i < 4; i++)
                #pragma unroll
                for (int k = 0; k < 4; k++)
                    o[i][k] += a[i] * bb[k];
        }
    }

    #pragma unroll
    for (int i = 0; i < 4; i++) {
        const float inv = 1.f / l_i[i];
        float4 v = make_float4(o[i][0]*inv, o[i][1]*inv, o[i][2]*inv, o[i][3]*inv);
        *(float4*)(AO + (size_t)(q0 + ty * 4 + i) * DMODEL + gh * HD + tx * 4) = v;
    }
}

// ===================== Launch =====================
extern "C" void kernel_launch(void* const* d_in, const int* in_sizes, int n_in,
                              void* d_out, int out_size)
{
    const float* x    = (const float*)d_in[0];   // (2, 2048, 2048)
    const float* Wqkv = (const float*)d_in[2];   // (2048, 3072)
    const float* Wout = (const float*)d_in[3];   // (2048, 2048)
    float* out = (float*)d_out;                  // (2, 2048, 2048)

    (void)cudaFuncSetAttribute(flash_attn_kernel,
                               cudaFuncAttributeMaxDynamicSharedMemorySize, ATTN_SMEM_BYTES);
    (void)cudaFuncSetAttribute(gemm_mma<1>,
                               cudaFuncAttributeMaxDynamicSharedMemorySize, GSMEM);
    (void)cudaFuncSetAttribute(gemm_mma<0>,
                               cudaFuncAttributeMaxDynamicSharedMemorySize, GSMEM);

    const int n4 = MROWS * DMODEL / 4;

    // 1) splits: x -> (xh, xl); W_qkv -> W^T hi/lo; W_out -> W^T hi/lo
    split_convert<<<(n4 + 255) / 256, 256>>>(x, n4, 0);
    transpose_convert<<<dim3(NQKV / 32, DMODEL / 32), dim3(32, 8)>>>(Wqkv, NQKV, 0);
    transpose_convert<<<dim3(DMODEL / 32, DMODEL / 32), dim3(32, 8)>>>(Wout, DMODEL, 1);

    // 2) qkv = x @ W_qkv  (mma.sync bf16x3) -> g_Q/g_K/g_V (fp32)
    gemm_mma<1><<<dim3(NQKV / 128, MROWS / 128), 256, GSMEM>>>(nullptr);

    // 3) causal flash attention (fp32) -> g_AO
    flash_attn_kernel<<<dim3(LSEQ / 64, 32, NB), AT_THREADS, ATTN_SMEM_BYTES>>>();

    // 4) AO -> (aoh, aol)
    split_convert<<<(n4 + 255) / 256, 256>>>(nullptr, n4, 1);

    // 5) out = AO @ W_out (mma.sync bf16x3)
    gemm_mma<0><<<dim3(DMODEL / 128, MROWS / 128), 256, GSMEM>>>(out);
}

// round 8
// speedup vs baseline: 2.5262x; 1.5651x over previous
#include <cuda_runtime.h>
#include <cuda_bf16.h>
#include <cstdint>

// Problem constants
#define LSEQ   2048
#define NB     2
#define DMODEL 2048
#define NQKV   3072
#define KVW    512
#define HD     64
#define MROWS  (NB * LSEQ)   // 4096

#define QSCALE 0.18033688011f   // 0.125 * log2(e): folded into Q at projection epilogue

// ---------------- scratch (device globals; no allocation allowed) ----------------
// bf16 hi/lo splits of activations and weights
__device__ __nv_bfloat16 g_xh [MROWS * DMODEL], g_xl [MROWS * DMODEL];
__device__ __nv_bfloat16 g_aoh[MROWS * DMODEL], g_aol[MROWS * DMODEL];
__device__ __nv_bfloat16 g_wqh[NQKV * DMODEL],  g_wql[NQKV * DMODEL];    // W_qkv^T (N,K)
__device__ __nv_bfloat16 g_woh[DMODEL * DMODEL], g_wol[DMODEL * DMODEL]; // W_out^T (N,K)
// Q/K/V in bf16 hi/lo (written by gemm<1> epilogue; Q pre-scaled by QSCALE)
// NOTE reshape semantics (plain reshape, no transpose): per batch, head gh's Q
// is the CONTIGUOUS (2048, 64) block at flat offset gh*LSEQ*HD (row stride 64);
// K/V head h likewise at h*LSEQ*HD in the (LSEQ*KVW) flat buffer.
__device__ __nv_bfloat16 g_Qh[MROWS * DMODEL], g_Ql[MROWS * DMODEL];
__device__ __nv_bfloat16 g_Kh[MROWS * KVW],    g_Kl[MROWS * KVW];
__device__ __nv_bfloat16 g_Vh[MROWS * KVW],    g_Vl[MROWS * KVW];

// ---------------- PTX helpers (portable ISA: sm_80+) ----------------
__device__ __forceinline__ uint32_t s2u(const void* p) {
    uint32_t a;
    asm("{ .reg .u64 t; cvta.to.shared.u64 t, %1; cvt.u32.u64 %0, t; }" : "=r"(a) : "l"(p));
    return a;
}

__device__ __forceinline__ void ldm4(uint32_t* r, uint32_t addr) {
    asm volatile("ldmatrix.sync.aligned.m8n8.x4.shared.b16 {%0,%1,%2,%3}, [%4];"
                 : "=r"(r[0]), "=r"(r[1]), "=r"(r[2]), "=r"(r[3]) : "r"(addr));
}
__device__ __forceinline__ void ldm4t(uint32_t* r, uint32_t addr) {
    asm volatile("ldmatrix.sync.aligned.m8n8.x4.trans.shared.b16 {%0,%1,%2,%3}, [%4];"
                 : "=r"(r[0]), "=r"(r[1]), "=r"(r[2]), "=r"(r[3]) : "r"(addr));
}

__device__ __forceinline__ void mma16816(float* d, const uint32_t* a, const uint32_t* b) {
    asm volatile("mma.sync.aligned.m16n8k16.row.col.f32.bf16.bf16.f32 "
                 "{%0,%1,%2,%3}, {%4,%5,%6,%7}, {%8,%9}, {%0,%1,%2,%3};"
                 : "+f"(d[0]), "+f"(d[1]), "+f"(d[2]), "+f"(d[3])
                 : "r"(a[0]), "r"(a[1]), "r"(a[2]), "r"(a[3]), "r"(b[0]), "r"(b[1]));
}

#define CPASYNC(dst, src) \
    asm volatile("cp.async.cg.shared.global [%0], [%1], 16;" :: "r"(dst), "l"(src))
#define CPCOMMIT() asm volatile("cp.async.commit_group;")
#define CPWAIT(n)  asm volatile("cp.async.wait_group %0;" :: "n"(n))

// pack two floats -> bf16x2 (lo in low half)
__device__ __forceinline__ uint32_t packbf(float lo_, float hi_) {
    __nv_bfloat162 t;
    t.x = __float2bfloat16(lo_);
    t.y = __float2bfloat16(hi_);
    return *(uint32_t*)&t;
}

// fast exp2 for t <= 0 (degree-6 Taylor of 2^f, rel err ~1.2e-5), FMA-pipe only
__device__ __forceinline__ float exp2p(float t) {
    t = fmaxf(t, -126.0f);
    float fl = floorf(t);
    float f  = t - fl;
    float p  = 1.5403530e-4f;
    p = p * f + 1.3333558e-3f;
    p = p * f + 9.6181291e-3f;
    p = p * f + 5.5504109e-2f;
    p = p * f + 2.4022651e-1f;
    p = p * f + 6.9314718e-1f;
    p = p * f + 1.0f;
    int i = (int)fl;
    return p * __int_as_float((uint32_t)(i + 127) << 23);
}

// ---------------- conversion kernels ----------------
__global__ void split_convert(const float* __restrict__ src, int n4)
{
    int i = blockIdx.x * blockDim.x + threadIdx.x;
    if (i >= n4) return;
    float4 v = ((const float4*)src)[i];
    float f[4] = {v.x, v.y, v.z, v.w};
    __nv_bfloat16 h[4], l[4];
    #pragma unroll
    for (int j = 0; j < 4; j++) {
        h[j] = __float2bfloat16(f[j]);
        l[j] = __float2bfloat16(f[j] - __bfloat162float(h[j]));
    }
    *(uint2*)(g_xh + 4 * (size_t)i) = *(uint2*)h;
    *(uint2*)(g_xl + 4 * (size_t)i) = *(uint2*)l;
}

// W (K=2048 rows, N cols) fp32 -> W^T (N rows, K cols) bf16 hi/lo
__global__ void transpose_convert(const float* __restrict__ in, int N, int sel)
{
    __shared__ float t[32][33];
    __nv_bfloat16* hi = sel ? g_woh : g_wqh;
    __nv_bfloat16* lo = sel ? g_wol : g_wql;
    const int n0 = blockIdx.x * 32, k0 = blockIdx.y * 32;
    const int tx = threadIdx.x, ty = threadIdx.y;
    #pragma unroll
    for (int j = 0; j < 32; j += 8)
        t[ty + j][tx] = in[(size_t)(k0 + ty + j) * N + n0 + tx];
    __syncthreads();
    #pragma unroll
    for (int j = 0; j < 32; j += 8) {
        float v = t[tx][ty + j];
        int n = n0 + ty + j, k = k0 + tx;
        __nv_bfloat16 h = __float2bfloat16(v);
        hi[(size_t)n * DMODEL + k] = h;
        lo[(size_t)n * DMODEL + k] = __float2bfloat16(v - __bfloat162float(h));
    }
}

// ---------------- mma.sync bf16x3 GEMM: 128x128 block, K=2048 ----------------
#define BKC 32
#define TROW 80                       // smem bytes per 32-bf16 row (ldmatrix conflict-free)
#define TILE_BYTES (128 * TROW)
#define STAGE_BYTES (4 * TILE_BYTES)
#define GSMEM (2 * STAGE_BYTES)       // 81920
#define NCHUNK (DMODEL / BKC)         // 64

// MODE 1: A=x, B=Wqkv^T; epilogue -> Qh/Ql (scaled), Kh/Kl, Vh/Vl (bf16 hi/lo)
// MODE 0: A=AO(hi/lo), B=Wout^T; epilogue -> Cout fp32
template<int MODE>
__global__ void __launch_bounds__(256)
gemm_mma(float* __restrict__ Cout)
{
    extern __shared__ char smem[];
    const uint32_t sb = s2u(smem);
    const int tid = threadIdx.x, wid = tid >> 5, lane = tid & 31;
    const int wm = wid >> 1, wn = wid & 1;

    const __nv_bfloat16 *Ah, *Al, *Bh, *Bl;
    if (MODE == 1) { Ah = g_xh;  Al = g_xl;  Bh = g_wqh; Bl = g_wql; }
    else           { Ah = g_aoh; Al = g_aol; Bh = g_woh; Bl = g_wol; }

    const int bm = blockIdx.y * 128;
    const int bn = blockIdx.x * 128;

    float acc[2][8][4];
    #pragma unroll
    for (int i = 0; i < 2; i++)
        #pragma unroll
        for (int j = 0; j < 8; j++)
            #pragma unroll
            for (int q = 0; q < 4; q++) acc[i][j][q] = 0.f;

    const int lrow0 = tid >> 2;
    const int lck   = tid & 3;

    auto issue_load = [&](int stage, int c) {
        const uint32_t so = sb + (uint32_t)stage * STAGE_BYTES;
        const int kc = c * BKC;
        const __nv_bfloat16* srcs[4] = {Ah, Al, Bh, Bl};
        #pragma unroll
        for (int t = 0; t < 4; t++) {
            const int rb = (t < 2) ? bm : bn;
            const __nv_bfloat16* s = srcs[t];
            #pragma unroll
            for (int half = 0; half < 2; half++) {
                int row = lrow0 + half * 64;
                uint32_t dst = so + (uint32_t)t * TILE_BYTES + row * TROW + lck * 16;
                const void* src = s + (size_t)(rb + row) * DMODEL + kc + lck * 8;
                CPASYNC(dst, src);
            }
        }
        CPCOMMIT();
    };

    issue_load(0, 0);

    for (int c = 0; c < NCHUNK; c++) {
        if (c + 1 < NCHUNK) issue_load((c + 1) & 1, c + 1);
        if (c + 1 < NCHUNK) { CPWAIT(1); } else { CPWAIT(0); }
        __syncthreads();

        const uint32_t so = sb + (uint32_t)(c & 1) * STAGE_BYTES;
        const uint32_t aq = (lane & 7) + ((lane >> 3) & 1) * 8;
        const uint32_t ak = (lane >> 4) * 8;
        const uint32_t bq = (lane & 7) + (lane >> 4) * 8;
        const uint32_t bk = ((lane >> 3) & 1) * 8;

        #pragma unroll
        for (int ks = 0; ks < 2; ks++) {
            uint32_t afh[2][4], afl[2][4];
            #pragma unroll
            for (int i = 0; i < 2; i++) {
                uint32_t addr = so + (wm * 32 + i * 16 + aq) * TROW + (ks * 16 + ak) * 2;
                ldm4(afh[i], addr);
                ldm4(afl[i], addr + TILE_BYTES);
            }
            uint32_t bfh[8][2], bfl[8][2];
            #pragma unroll
            for (int jj = 0; jj < 4; jj++) {
                uint32_t addr = so + 2 * TILE_BYTES
                              + (wn * 64 + jj * 16 + bq) * TROW + (ks * 16 + bk) * 2;
                uint32_t r[4];
                ldm4(r, addr);
                bfh[jj*2][0] = r[0]; bfh[jj*2][1] = r[1];
                bfh[jj*2+1][0] = r[2]; bfh[jj*2+1][1] = r[3];
                ldm4(r, addr + TILE_BYTES);
                bfl[jj*2][0] = r[0]; bfl[jj*2][1] = r[1];
                bfl[jj*2+1][0] = r[2]; bfl[jj*2+1][1] = r[3];
            }
            #pragma unroll
            for (int i = 0; i < 2; i++)
                #pragma unroll
                for (int j = 0; j < 8; j++) {
                    mma16816(acc[i][j], afh[i], bfh[j]);
                    mma16816(acc[i][j], afh[i], bfl[j]);
                    mma16816(acc[i][j], afl[i], bfh[j]);
                }
        }
        __syncthreads();
    }

    // ---- epilogue ----
    const int g = lane >> 2, tg = lane & 3;
    if (MODE == 0) {
        #pragma unroll
        for (int i = 0; i < 2; i++) {
            const int r0 = bm + wm * 32 + i * 16 + g;
            #pragma unroll
            for (int j = 0; j < 8; j++) {
                const int cc = bn + wn * 64 + j * 8 + tg * 2;
                *(float2*)(Cout + (size_t)r0 * DMODEL + cc)       = make_float2(acc[i][j][0], acc[i][j][1]);
                *(float2*)(Cout + (size_t)(r0 + 8) * DMODEL + cc) = make_float2(acc[i][j][2], acc[i][j][3]);
            }
        }
    } else {
        // write bf16 hi/lo to Q (scaled) / K / V  (block-uniform region: bn mult of 128)
        __nv_bfloat16 *dh, *dl; int ldd, c0; float scale;
        if (bn < DMODEL)            { dh = g_Qh; dl = g_Ql; ldd = DMODEL; c0 = bn;                scale = QSCALE; }
        else if (bn < DMODEL + KVW) { dh = g_Kh; dl = g_Kl; ldd = KVW;   c0 = bn - DMODEL;        scale = 1.f; }
        else                        { dh = g_Vh; dl = g_Vl; ldd = KVW;   c0 = bn - DMODEL - KVW;  scale = 1.f; }
        #pragma unroll
        for (int i = 0; i < 2; i++) {
            const int r0 = bm + wm * 32 + i * 16 + g;   // global row 0..4095
            #pragma unroll
            for (int j = 0; j < 8; j++) {
                const int cc = c0 + wn * 64 + j * 8 + tg * 2;
                #pragma unroll
                for (int rr = 0; rr < 2; rr++) {
                    float v0 = acc[i][j][rr*2 + 0] * scale;
                    float v1 = acc[i][j][rr*2 + 1] * scale;
                    __nv_bfloat16 h0 = __float2bfloat16(v0);
                    __nv_bfloat16 h1 = __float2bfloat16(v1);
                    float l0 = v0 - __bfloat162float(h0);
                    float l1 = v1 - __bfloat162float(h1);
                    size_t off = (size_t)(r0 + rr * 8) * ldd + cc;
                    __nv_bfloat162 hp; hp.x = h0; hp.y = h1;
                    *(uint32_t*)(dh + off) = *(uint32_t*)&hp;
                    *(uint32_t*)(dl + off) = packbf(l0, l1);
                }
            }
        }
    }
}

// ---------------- flash attention, mma.sync bf16x3, Br=128 Bc=64 ----------------
#define FA_T 256
#define FTROW 144                       // 64 bf16 = 128B data + 16B pad (conflict-free)
#define QSM_B (128 * FTROW)             // 18432 per Q version
#define FKV_TILE (64 * FTROW)           // 9216
#define FSTAGE (4 * FKV_TILE)           // Kh,Kl,Vh,Vl = 36864
#define FA_SMEM (2 * QSM_B + 2 * FSTAGE) // 110592

__global__ void __launch_bounds__(FA_T)
fa_mma()
{
    extern __shared__ char smem[];
    const uint32_t sb = s2u(smem);
    const int tid = threadIdx.x, wm = tid >> 5, lane = tid & 31;
    const int g = lane >> 2, tg = lane & 3;

    const int qt = blockIdx.x;           // 0..15 (128-row q tiles)
    const int gh = blockIdx.y;           // 0..31
    const int b  = blockIdx.z;
    const int h  = gh & 7;
    const int q0 = qt * 128;
    const int jmax = 2 * qt + 1;

    // Reshape semantics (plain reshape, no transpose): head blocks are CONTIGUOUS
    // (LSEQ, 64) slabs; row stride HD, not DMODEL/KVW.
    const size_t qbase = (size_t)b * LSEQ * DMODEL + (size_t)gh * LSEQ * HD;
    const size_t kbase = (size_t)b * LSEQ * KVW + (size_t)h * LSEQ * HD;

    // ---- prologue: load Q (hi/lo) + KV stage 0 ----
    {
        #pragma unroll
        for (int v = 0; v < 2; v++) {
            const __nv_bfloat16* src = v ? g_Ql : g_Qh;
            #pragma unroll
            for (int i = 0; i < 4; i++) {
                int c = tid + i * 256;
                int row = c >> 3, cx = c & 7;
                uint32_t dst = sb + (uint32_t)v * QSM_B + row * FTROW + cx * 16;
                CPASYNC(dst, src + qbase + (size_t)(q0 + row) * HD + cx * 8);
            }
        }
        CPCOMMIT();
    }

    auto issue_kv = [&](int stage, int jt) {
        const uint32_t so = sb + 2 * QSM_B + (uint32_t)stage * FSTAGE;
        const int j0 = jt * 64;
        const __nv_bfloat16* srcs[4] = {g_Kh, g_Kl, g_Vh, g_Vl};
        #pragma unroll
        for (int t = 0; t < 4; t++) {
            #pragma unroll
            for (int k = 0; k < 2; k++) {
                int c = tid + k * 256;
                int row = c >> 3, cx = c & 7;
                uint32_t dst = so + (uint32_t)t * FKV_TILE + row * FTROW + cx * 16;
                CPASYNC(dst, srcs[t] + kbase + (size_t)(j0 + row) * HD + cx * 8);
            }
        }
        CPCOMMIT();
    };

    issue_kv(0, 0);
    CPWAIT(0);
    __syncthreads();

    // Q fragments (register-resident for the whole block)
    const uint32_t aq = (lane & 7) + ((lane >> 3) & 1) * 8;
    const uint32_t ak = (lane >> 4) * 8;
    const uint32_t bq = (lane & 7) + (lane >> 4) * 8;
    const uint32_t bk = ((lane >> 3) & 1) * 8;

    uint32_t qhf[4][4], qlf[4][4];
    #pragma unroll
    for (int ks = 0; ks < 4; ks++) {
        uint32_t addr = sb + (wm * 16 + aq) * FTROW + (ks * 16 + ak) * 2;
        ldm4(qhf[ks], addr);
        ldm4(qlf[ks], addr + QSM_B);
    }

    float of[8][4];
    #pragma unroll
    for (int a = 0; a < 8; a++)
        #pragma unroll
        for (int e = 0; e < 4; e++) of[a][e] = 0.f;
    float m_i[2] = {-1e30f, -1e30f}, l_i[2] = {0.f, 0.f};

    for (int jt = 0; jt <= jmax; jt++) {
        if (jt + 1 <= jmax) { issue_kv((jt + 1) & 1, jt + 1); CPWAIT(1); }
        else                { CPWAIT(0); }
        __syncthreads();

        // fully-masked warps (first half at the odd diagonal tile) skip compute
        const bool skip = (q0 + wm * 16 + 15) < jt * 64;
        if (!skip) {
            const uint32_t so = sb + 2 * QSM_B + (uint32_t)(jt & 1) * FSTAGE;

            // ---- S = Q K^T (base-2 logits; Q pre-scaled) ----
            float sf[8][4];
            #pragma unroll
            for (int a = 0; a < 8; a++)
                #pragma unroll
                for (int e = 0; e < 4; e++) sf[a][e] = 0.f;

            #pragma unroll
            for (int ks = 0; ks < 4; ks++) {
                #pragma unroll
                for (int nb = 0; nb < 4; nb++) {
                    uint32_t addr = so + (nb * 16 + bq) * FTROW + (ks * 16 + bk) * 2;
                    uint32_t rh[4], rl[4];
                    ldm4(rh, addr);
                    ldm4(rl, addr + FKV_TILE);
                    mma16816(sf[2*nb],   qhf[ks], &rh[0]);
                    mma16816(sf[2*nb],   qhf[ks], &rl[0]);
                    mma16816(sf[2*nb],   qlf[ks], &rh[0]);
                    mma16816(sf[2*nb+1], qhf[ks], &rh[2]);
                    mma16816(sf[2*nb+1], qhf[ks], &rl[2]);
                    mma16816(sf[2*nb+1], qlf[ks], &rh[2]);
                }
            }

            // ---- online softmax (base 2) per row-half ----
            #pragma unroll
            for (int hh = 0; hh < 2; hh++) {
                const int grow = q0 + wm * 16 + hh * 8 + g;
                float mx = -1e30f;
                #pragma unroll
                for (int a = 0; a < 8; a++)
                    #pragma unroll
                    for (int e = 0; e < 2; e++) {
                        int col = jt * 64 + a * 8 + 2 * tg + e;
                        float v = sf[a][2*hh + e];
                        if (col > grow) v = -1e30f;
                        sf[a][2*hh + e] = v;
                        mx = fmaxf(mx, v);
                    }
                mx = fmaxf(mx, __shfl_xor_sync(0xffffffffu, mx, 1));
                mx = fmaxf(mx, __shfl_xor_sync(0xffffffffu, mx, 2));
                const float mnew  = fmaxf(m_i[hh], mx);
                const float alpha = exp2p(m_i[hh] - mnew);
                float rs = 0.f;
                #pragma unroll
                for (int a = 0; a < 8; a++)
                    #pragma unroll
                    for (int e = 0; e < 2; e++) {
                        float p = exp2p(sf[a][2*hh + e] - mnew);
                        sf[a][2*hh + e] = p;
                        rs += p;
                    }
                rs += __shfl_xor_sync(0xffffffffu, rs, 1);
                rs += __shfl_xor_sync(0xffffffffu, rs, 2);
                l_i[hh] = l_i[hh] * alpha + rs;
                m_i[hh] = mnew;
                #pragma unroll
                for (int a = 0; a < 8; a++)
                    #pragma unroll
                    for (int e = 0; e < 2; e++) of[a][2*hh + e] *= alpha;
            }

            // ---- O += P V  (P repacked C->A in registers, hi/lo split) ----
            // A-frag reg order {(g,k-lo),(g+8,k-lo),(g,k-hi),(g+8,k-hi)} is built
            // exactly from C atoms 2ks (j-lo) and 2ks+1 (j-hi).
            #pragma unroll
            for (int ks = 0; ks < 4; ks++) {
                uint32_t pah[4], pal[4];
                #pragma unroll
                for (int q = 0; q < 4; q++) {
                    float p0 = sf[2*ks + (q >> 1)][(q & 1) * 2 + 0];
                    float p1 = sf[2*ks + (q >> 1)][(q & 1) * 2 + 1];
                    __nv_bfloat16 h0 = __float2bfloat16(p0);
                    __nv_bfloat16 h1 = __float2bfloat16(p1);
                    __nv_bfloat162 hp; hp.x = h0; hp.y = h1;
                    pah[q] = *(uint32_t*)&hp;
                    pal[q] = packbf(p0 - __bfloat162float(h0), p1 - __bfloat162float(h1));
                }

                #pragma unroll
                for (int nb = 0; nb < 4; nb++) {
                    uint32_t addr = so + 2 * FKV_TILE + (ks * 16 + aq) * FTROW + (nb * 16 + ak) * 2;
                    uint32_t rh[4], rl[4];
                    ldm4t(rh, addr);
                    ldm4t(rl, addr + FKV_TILE);
                    mma16816(of[2*nb],   pah, &rh[0]);
                    mma16816(of[2*nb],   pah, &rl[0]);
                    mma16816(of[2*nb],   pal, &rh[0]);
                    mma16816(of[2*nb+1], pah, &rh[2]);
                    mma16816(of[2*nb+1], pah, &rl[2]);
                    mma16816(of[2*nb+1], pal, &rh[2]);
                }
            }
        }
        __syncthreads();
    }

    // ---- epilogue: normalize, split to bf16 hi/lo, write AO ----
    // Output rearrange 'b g h l d -> b l (g h d)' IS the standard layout:
    // row l, cols gh*64 + d, row stride DMODEL.
    const size_t aobase = (size_t)b * LSEQ * DMODEL;
    #pragma unroll
    for (int hh = 0; hh < 2; hh++) {
        const float inv = 1.f / l_i[hh];
        const int row = q0 + wm * 16 + hh * 8 + g;
        #pragma unroll
        for (int a = 0; a < 8; a++) {
            float o0 = of[a][2*hh + 0] * inv;
            float o1 = of[a][2*hh + 1] * inv;
            __nv_bfloat16 h0 = __float2bfloat16(o0);
            __nv_bfloat16 h1 = __float2bfloat16(o1);
            __nv_bfloat162 hp; hp.x = h0; hp.y = h1;
            size_t off = aobase + (size_t)row * DMODEL + gh * HD + a * 8 + 2 * tg;
            *(uint32_t*)(g_aoh + off) = *(uint32_t*)&hp;
            *(uint32_t*)(g_aol + off) = packbf(o0 - __bfloat162float(h0), o1 - __bfloat162float(h1));
        }
    }
}

// ===================== Launch =====================
extern "C" void kernel_launch(void* const* d_in, const int* in_sizes, int n_in,
                              void* d_out, int out_size)
{
    const float* x    = (const float*)d_in[0];   // (2, 2048, 2048)
    const float* Wqkv = (const float*)d_in[2];   // (2048, 3072)
    const float* Wout = (const float*)d_in[3];   // (2048, 2048)
    float* out = (float*)d_out;                  // (2, 2048, 2048)

    (void)cudaFuncSetAttribute(gemm_mma<1>,
                               cudaFuncAttributeMaxDynamicSharedMemorySize, GSMEM);
    (void)cudaFuncSetAttribute(gemm_mma<0>,
                               cudaFuncAttributeMaxDynamicSharedMemorySize, GSMEM);
    (void)cudaFuncSetAttribute(fa_mma,
                               cudaFuncAttributeMaxDynamicSharedMemorySize, FA_SMEM);

    const int n4 = MROWS * DMODEL / 4;

    split_convert<<<(n4 + 255) / 256, 256>>>(x, n4);
    transpose_convert<<<dim3(NQKV / 32, DMODEL / 32), dim3(32, 8)>>>(Wqkv, NQKV, 0);
    transpose_convert<<<dim3(DMODEL / 32, DMODEL / 32), dim3(32, 8)>>>(Wout, DMODEL, 1);

    // qkv projection -> Q(scaled)/K/V bf16 hi/lo
    gemm_mma<1><<<dim3(NQKV / 128, MROWS / 128), 256, GSMEM>>>(nullptr);

    // causal flash attention (tensor core) -> aoh/aol
    fa_mma<<<dim3(LSEQ / 128, 32, NB), FA_T, FA_SMEM>>>();

    // output projection
    gemm_mma<0><<<dim3(DMODEL / 128, MROWS / 128), 256, GSMEM>>>(out);
}